// round 1
// baseline (speedup 1.0000x reference)
#include <cuda_runtime.h>
#include <cuda_bf16.h>
#include <math.h>

// g_bounds: [0]=a_max [1]=b_max [2]=c_max [3]=nc [4]=nb*nc [5]=N
__device__ int g_bounds[6];

__device__ __forceinline__ void cross3d(const double* u, const double* v, double* o) {
    o[0] = u[1] * v[2] - u[2] * v[1];
    o[1] = u[2] * v[0] - u[0] * v[2];
    o[2] = u[0] * v[1] - u[1] * v[0];
}

__device__ __forceinline__ int nmax_dev(const double* u, const double* v,
                                        const double* dr, double cutoff, double vol) {
    double cr[3];
    cross3d(u, v, cr);
    double ln = sqrt(cr[0] * cr[0] + cr[1] * cr[1] + cr[2] * cr[2]);
    // reference: dot(dr, cr/ln)
    double d = fabs(dr[0] * (cr[0] / ln) + dr[1] * (cr[1] / ln) + dr[2] * (cr[2] / ln));
    double val = floor((cutoff + d) / vol * ln);
    long long m = (long long)val;
    if (m > 100000) m = 100000;
    if (m < 0) m = 0;
    return (int)m;
}

__global__ void bounds_kernel(const float* __restrict__ cell,
                              const float* __restrict__ cutoff_p,
                              const float* __restrict__ r1,
                              const float* __restrict__ r2) {
    double a[3], b[3], c[3], dr[3];
    #pragma unroll
    for (int d = 0; d < 3; d++) {
        a[d] = (double)cell[d];
        b[d] = (double)cell[3 + d];
        c[d] = (double)cell[6 + d];
        dr[d] = (double)r2[d] - (double)r1[d];
    }
    double cutoff = (double)cutoff_p[0];
    double bc[3];
    cross3d(b, c, bc);
    double vol = fabs(a[0] * bc[0] + a[1] * bc[1] + a[2] * bc[2]);

    int a_max = nmax_dev(b, c, dr, cutoff, vol);
    int b_max = nmax_dev(a, c, dr, cutoff, vol);
    int c_max = nmax_dev(a, b, dr, cutoff, vol);

    int na = 2 * a_max + 1, nb = 2 * b_max + 1, nc = 2 * c_max + 1;
    g_bounds[0] = a_max;
    g_bounds[1] = b_max;
    g_bounds[2] = c_max;
    g_bounds[3] = nc;
    g_bounds[4] = nb * nc;
    g_bounds[5] = na * nb * nc;
}

__global__ void __launch_bounds__(256) periodic_kernel(
    const float* __restrict__ cell,
    const float* __restrict__ cutoff_p,
    const float* __restrict__ r1,
    const float* __restrict__ r2,
    float* __restrict__ out) {
    const int a_max = g_bounds[0];
    const int b_max = g_bounds[1];
    const int c_max = g_bounds[2];
    const int nc    = g_bounds[3];
    const int nbc   = g_bounds[4];
    const int N     = g_bounds[5];

    int t = blockIdx.x * blockDim.x + threadIdx.x;
    int base = t * 4;
    if (base >= N) return;

    // cell rows (broadcast loads, L1-hit after first warp)
    const float c00 = cell[0], c01 = cell[1], c02 = cell[2];
    const float c10 = cell[3], c11 = cell[4], c12 = cell[5];
    const float c20 = cell[6], c21 = cell[7], c22 = cell[8];
    const float drx = r2[0] - r1[0];
    const float dry = r2[1] - r1[1];
    const float drz = r2[2] - r1[2];
    const float co  = cutoff_p[0];
    const float cut2 = co * co;

    // decompose base -> (i, j, k), i outer / k inner (matches meshgrid 'ij' ravel)
    unsigned ub = (unsigned)base;
    unsigned ii = ub / (unsigned)nbc;
    unsigned rem = ub - ii * (unsigned)nbc;
    unsigned jj = rem / (unsigned)nc;
    unsigned kk = rem - jj * (unsigned)nc;
    int i = (int)ii - a_max;
    int j = (int)jj - b_max;
    int k = (int)kk - c_max;

    float v[12], q[12], mm[4];
    const int cnt = (base + 4 <= N) ? 4 : (N - base);

    #pragma unroll
    for (int e = 0; e < 4; e++) {
        float fi = (float)i, fj = (float)j, fk = (float)k;
        float x = fi * c00 + fj * c10 + fk * c20 + drx;
        float y = fi * c01 + fj * c11 + fk * c21 + dry;
        float z = fi * c02 + fj * c12 + fk * c22 + drz;
        float s = x * x + y * y + z * z;
        bool m = s < cut2;
        v[3 * e + 0] = m ? x : 0.0f;
        v[3 * e + 1] = m ? y : 0.0f;
        v[3 * e + 2] = m ? z : 0.0f;
        q[3 * e + 0] = m ? fi : 0.0f;
        q[3 * e + 1] = m ? fj : 0.0f;
        q[3 * e + 2] = m ? fk : 0.0f;
        mm[e] = m ? 1.0f : 0.0f;
        // advance (i,j,k) by one linear index with carry
        k++;
        if (k > c_max) {
            k = -c_max;
            j++;
            if (j > b_max) {
                j = -b_max;
                i++;
            }
        }
    }

    float* vbase = out;                          // [N*3] vectors
    float* qbase = out + 3 * (size_t)N;          // [N*3] cell indices (as float)
    float* mbase = out + 6 * (size_t)N;          // [N]   mask (as float)

    if (cnt == 4) {
        // vectors region: base*3 floats from a 16B-aligned base -> 48B-aligned: 3x STG.128
        float4* vp = (float4*)(vbase + (size_t)base * 3);
        vp[0] = make_float4(v[0], v[1], v[2], v[3]);
        vp[1] = make_float4(v[4], v[5], v[6], v[7]);
        vp[2] = make_float4(v[8], v[9], v[10], v[11]);
        // indices region: byte offset 12N ≡ 4 (mod 16) since N odd -> scalar stores
        float* qp = qbase + (size_t)base * 3;
        #pragma unroll
        for (int x2 = 0; x2 < 12; x2++) qp[x2] = q[x2];
        // mask region: byte offset 24N ≡ 8 (mod 16) -> 8B aligned: 2x STG.64
        float2* mp = (float2*)(mbase + base);
        mp[0] = make_float2(mm[0], mm[1]);
        mp[1] = make_float2(mm[2], mm[3]);
    } else {
        #pragma unroll
        for (int e = 0; e < 4; e++) {
            if (e < cnt) {
                int idx = base + e;
                vbase[(size_t)idx * 3 + 0] = v[3 * e + 0];
                vbase[(size_t)idx * 3 + 1] = v[3 * e + 1];
                vbase[(size_t)idx * 3 + 2] = v[3 * e + 2];
                qbase[(size_t)idx * 3 + 0] = q[3 * e + 0];
                qbase[(size_t)idx * 3 + 1] = q[3 * e + 1];
                qbase[(size_t)idx * 3 + 2] = q[3 * e + 2];
                mbase[idx] = mm[e];
            }
        }
    }
}

extern "C" void kernel_launch(void* const* d_in, const int* in_sizes, int n_in,
                              void* d_out, int out_size) {
    const float* cell   = (const float*)d_in[0];
    const float* cutoff = (const float*)d_in[1];
    const float* r1     = (const float*)d_in[2];
    const float* r2     = (const float*)d_in[3];
    float* out = (float*)d_out;

    // Host-side static grid size from out_size = 7*N
    long long Nhost = (long long)out_size / 7;
    long long nthreads = (Nhost + 3) / 4;
    int block = 256;
    long long grid = (nthreads + block - 1) / block;
    if (grid < 1) grid = 1;

    bounds_kernel<<<1, 1>>>(cell, cutoff, r1, r2);
    periodic_kernel<<<(unsigned)grid, block>>>(cell, cutoff, r1, r2, out);
}

// round 2
// speedup vs baseline: 2.0572x; 2.0572x over previous
#include <cuda_runtime.h>
#include <cuda_bf16.h>
#include <math.h>
#include <stdint.h>

// g_bounds: [0]=a_max [1]=b_max [2]=c_max [3]=nc [4]=nb*nc [5]=N
__device__ int g_bounds[6];

__device__ __forceinline__ void cross3d(const double* u, const double* v, double* o) {
    o[0] = u[1] * v[2] - u[2] * v[1];
    o[1] = u[2] * v[0] - u[0] * v[2];
    o[2] = u[0] * v[1] - u[1] * v[0];
}

__device__ __forceinline__ int nmax_dev(const double* u, const double* v,
                                        const double* dr, double cutoff, double vol) {
    double cr[3];
    cross3d(u, v, cr);
    double ln = sqrt(cr[0] * cr[0] + cr[1] * cr[1] + cr[2] * cr[2]);
    double d = fabs(dr[0] * (cr[0] / ln) + dr[1] * (cr[1] / ln) + dr[2] * (cr[2] / ln));
    double val = floor((cutoff + d) / vol * ln);
    long long m = (long long)val;
    if (m > 100000) m = 100000;
    if (m < 0) m = 0;
    return (int)m;
}

__global__ void bounds_kernel(const float* __restrict__ cell,
                              const float* __restrict__ cutoff_p,
                              const float* __restrict__ r1,
                              const float* __restrict__ r2) {
    double a[3], b[3], c[3], dr[3];
    #pragma unroll
    for (int d = 0; d < 3; d++) {
        a[d] = (double)cell[d];
        b[d] = (double)cell[3 + d];
        c[d] = (double)cell[6 + d];
        dr[d] = (double)r2[d] - (double)r1[d];
    }
    double cutoff = (double)cutoff_p[0];
    double bc[3];
    cross3d(b, c, bc);
    double vol = fabs(a[0] * bc[0] + a[1] * bc[1] + a[2] * bc[2]);

    int a_max = nmax_dev(b, c, dr, cutoff, vol);
    int b_max = nmax_dev(a, c, dr, cutoff, vol);
    int c_max = nmax_dev(a, b, dr, cutoff, vol);

    int na = 2 * a_max + 1, nb = 2 * b_max + 1, nc = 2 * c_max + 1;
    g_bounds[0] = a_max;
    g_bounds[1] = b_max;
    g_bounds[2] = c_max;
    g_bounds[3] = nc;
    g_bounds[4] = nb * nc;
    g_bounds[5] = na * nb * nc;
}

// Alignment-general coalesced copy: smem -> gmem, lanes contiguous.
// dst is at least 4B aligned. Handles head/tail scalars around a float4 body.
__device__ __forceinline__ void copy_region(float* __restrict__ dst,
                                            const float* __restrict__ src,
                                            int n, int tid, int nthreads) {
    if (n <= 0) return;
    uintptr_t addr = (uintptr_t)dst;
    int head = (int)(((16u - (unsigned)(addr & 15u)) & 15u) >> 2);
    if (head > n) head = n;
    for (int i = tid; i < head; i += nthreads) dst[i] = src[i];
    int body = (n - head) >> 2;
    float4* d4 = (float4*)(dst + head);
    const float* s = src + head;
    for (int i = tid; i < body; i += nthreads) {
        d4[i] = make_float4(s[4 * i], s[4 * i + 1], s[4 * i + 2], s[4 * i + 3]);
    }
    int done = head + (body << 2);
    for (int i = done + tid; i < n; i += nthreads) dst[i] = src[i];
}

#define ELEMS_PER_BLOCK 1024
#define BLOCK_THREADS 256

__global__ void __launch_bounds__(BLOCK_THREADS) periodic_kernel(
    const float* __restrict__ cell,
    const float* __restrict__ cutoff_p,
    const float* __restrict__ r1,
    const float* __restrict__ r2,
    float* __restrict__ out) {
    __shared__ float s_v[ELEMS_PER_BLOCK * 3];  // 12 KB, interleaved xyz
    __shared__ float s_q[ELEMS_PER_BLOCK * 3];  // 12 KB, interleaved ijk
    __shared__ float s_m[ELEMS_PER_BLOCK];      //  4 KB

    const int a_max = g_bounds[0];
    const int b_max = g_bounds[1];
    const int c_max = g_bounds[2];
    const int nc    = g_bounds[3];
    const int nbc   = g_bounds[4];
    const int N     = g_bounds[5];

    const int tid = threadIdx.x;
    const int blockElemStart = blockIdx.x * ELEMS_PER_BLOCK;
    if (blockElemStart >= N) return;

    // ---- compute phase: 4 consecutive elements per thread into smem ----
    {
        const float c00 = cell[0], c01 = cell[1], c02 = cell[2];
        const float c10 = cell[3], c11 = cell[4], c12 = cell[5];
        const float c20 = cell[6], c21 = cell[7], c22 = cell[8];
        const float drx = r2[0] - r1[0];
        const float dry = r2[1] - r1[1];
        const float drz = r2[2] - r1[2];
        const float co  = cutoff_p[0];
        const float cut2 = co * co;

        int base = blockElemStart + tid * 4;  // may exceed N (tail block) — smem garbage is OK

        // decompose base -> (i, j, k)
        unsigned ub = (unsigned)min(base, N - 1);
        unsigned ii = ub / (unsigned)nbc;
        unsigned rem = ub - ii * (unsigned)nbc;
        unsigned jj = rem / (unsigned)nc;
        unsigned kk = rem - jj * (unsigned)nc;
        int i = (int)ii - a_max;
        int j = (int)jj - b_max;
        int k = (int)kk - c_max;

        float v[12], q[12], mm[4];
        #pragma unroll
        for (int e = 0; e < 4; e++) {
            float fi = (float)i, fj = (float)j, fk = (float)k;
            float x = fi * c00 + fj * c10 + fk * c20 + drx;
            float y = fi * c01 + fj * c11 + fk * c21 + dry;
            float z = fi * c02 + fj * c12 + fk * c22 + drz;
            float ss = x * x + y * y + z * z;
            bool m = ss < cut2;
            v[3 * e + 0] = m ? x : 0.0f;
            v[3 * e + 1] = m ? y : 0.0f;
            v[3 * e + 2] = m ? z : 0.0f;
            q[3 * e + 0] = m ? fi : 0.0f;
            q[3 * e + 1] = m ? fj : 0.0f;
            q[3 * e + 2] = m ? fk : 0.0f;
            mm[e] = m ? 1.0f : 0.0f;
            k++;
            if (k > c_max) {
                k = -c_max;
                j++;
                if (j > b_max) {
                    j = -b_max;
                    i++;
                }
            }
        }

        // smem stores: STS.128 with 48B lane stride -> conflict-free
        float4* sv4 = (float4*)(s_v + tid * 12);
        sv4[0] = make_float4(v[0], v[1], v[2], v[3]);
        sv4[1] = make_float4(v[4], v[5], v[6], v[7]);
        sv4[2] = make_float4(v[8], v[9], v[10], v[11]);
        float4* sq4 = (float4*)(s_q + tid * 12);
        sq4[0] = make_float4(q[0], q[1], q[2], q[3]);
        sq4[1] = make_float4(q[4], q[5], q[6], q[7]);
        sq4[2] = make_float4(q[8], q[9], q[10], q[11]);
        float4* sm4 = (float4*)(s_m + tid * 4);
        sm4[0] = make_float4(mm[0], mm[1], mm[2], mm[3]);
    }
    __syncthreads();

    // ---- copy phase: lane-contiguous smem -> gmem ----
    int cnt = N - blockElemStart;
    if (cnt > ELEMS_PER_BLOCK) cnt = ELEMS_PER_BLOCK;

    float* vdst = out + (size_t)blockElemStart * 3;
    float* qdst = out + 3 * (size_t)N + (size_t)blockElemStart * 3;
    float* mdst = out + 6 * (size_t)N + (size_t)blockElemStart;

    copy_region(vdst, s_v, cnt * 3, tid, BLOCK_THREADS);
    copy_region(qdst, s_q, cnt * 3, tid, BLOCK_THREADS);
    copy_region(mdst, s_m, cnt, tid, BLOCK_THREADS);
}

extern "C" void kernel_launch(void* const* d_in, const int* in_sizes, int n_in,
                              void* d_out, int out_size) {
    const float* cell   = (const float*)d_in[0];
    const float* cutoff = (const float*)d_in[1];
    const float* r1     = (const float*)d_in[2];
    const float* r2     = (const float*)d_in[3];
    float* out = (float*)d_out;

    long long Nhost = (long long)out_size / 7;
    long long grid = (Nhost + ELEMS_PER_BLOCK - 1) / ELEMS_PER_BLOCK;
    if (grid < 1) grid = 1;

    bounds_kernel<<<1, 1>>>(cell, cutoff, r1, r2);
    periodic_kernel<<<(unsigned)grid, BLOCK_THREADS>>>(cell, cutoff, r1, r2, out);
}

// round 3
// speedup vs baseline: 2.7578x; 1.3406x over previous
#include <cuda_runtime.h>
#include <cuda_bf16.h>
#include <math.h>
#include <stdint.h>

// g_bounds: [0]=a_max [1]=b_max [2]=c_max [3]=nc [4]=nb*nc [5]=N
__device__ int g_bounds[6];

__device__ __forceinline__ void cross3d(const double* u, const double* v, double* o) {
    o[0] = u[1] * v[2] - u[2] * v[1];
    o[1] = u[2] * v[0] - u[0] * v[2];
    o[2] = u[0] * v[1] - u[1] * v[0];
}

__device__ __forceinline__ int nmax_dev(const double* u, const double* v,
                                        const double* dr, double cutoff, double vol) {
    double cr[3];
    cross3d(u, v, cr);
    double ln = sqrt(cr[0] * cr[0] + cr[1] * cr[1] + cr[2] * cr[2]);
    double d = fabs(dr[0] * (cr[0] / ln) + dr[1] * (cr[1] / ln) + dr[2] * (cr[2] / ln));
    double val = floor((cutoff + d) / vol * ln);
    long long m = (long long)val;
    if (m > 100000) m = 100000;
    if (m < 0) m = 0;
    return (int)m;
}

__global__ void bounds_kernel(const float* __restrict__ cell,
                              const float* __restrict__ cutoff_p,
                              const float* __restrict__ r1,
                              const float* __restrict__ r2) {
    double a[3], b[3], c[3], dr[3];
    #pragma unroll
    for (int d = 0; d < 3; d++) {
        a[d] = (double)cell[d];
        b[d] = (double)cell[3 + d];
        c[d] = (double)cell[6 + d];
        dr[d] = (double)r2[d] - (double)r1[d];
    }
    double cutoff = (double)cutoff_p[0];
    double bc[3];
    cross3d(b, c, bc);
    double vol = fabs(a[0] * bc[0] + a[1] * bc[1] + a[2] * bc[2]);

    int a_max = nmax_dev(b, c, dr, cutoff, vol);
    int b_max = nmax_dev(a, c, dr, cutoff, vol);
    int c_max = nmax_dev(a, b, dr, cutoff, vol);

    int na = 2 * a_max + 1, nb = 2 * b_max + 1, nc = 2 * c_max + 1;
    g_bounds[0] = a_max;
    g_bounds[1] = b_max;
    g_bounds[2] = c_max;
    g_bounds[3] = nc;
    g_bounds[4] = nb * nc;
    g_bounds[5] = na * nb * nc;
}

#define EPB 1024
#define BT 256
#define OFF_Q 3072
#define OFF_M 6144
#define S_FLOATS 7168  // 28672 bytes

__device__ __forceinline__ uint32_t smem_u32(const void* p) {
    return (uint32_t)__cvta_generic_to_shared(p);
}

__global__ void __launch_bounds__(BT) periodic_kernel(
    const float* __restrict__ cell,
    const float* __restrict__ cutoff_p,
    const float* __restrict__ r1,
    const float* __restrict__ r2,
    float* __restrict__ out) {
    __shared__ __align__(16) float S[S_FLOATS];

    const int a_max = g_bounds[0];
    const int b_max = g_bounds[1];
    const int c_max = g_bounds[2];
    const int nc    = g_bounds[3];
    const int nbc   = g_bounds[4];
    const int N     = g_bounds[5];

    const int tid = threadIdx.x;
    const long long B0l = (long long)blockIdx.x * EPB;
    if (B0l >= N) return;
    const int B0 = (int)B0l;

    const float c00 = cell[0], c01 = cell[1], c02 = cell[2];
    const float c10 = cell[3], c11 = cell[4], c12 = cell[5];
    const float c20 = cell[6], c21 = cell[7], c22 = cell[8];
    const float drx = r2[0] - r1[0];
    const float dry = r2[1] - r1[1];
    const float drz = r2[2] - r1[2];
    const float co  = cutoff_p[0];
    const float cut2 = co * co;

    float* __restrict__ vb = out;
    float* __restrict__ qb = out + 3 * (size_t)N;
    float* __restrict__ mb = out + 6 * (size_t)N;

    const bool full = (B0 + EPB) <= N;

    if (!full) {
        // tail block: scalar fallback (one block, ~N%1024 elements)
        for (int idx = B0 + tid; idx < N; idx += BT) {
            unsigned ub = (unsigned)idx;
            unsigned ii = ub / (unsigned)nbc;
            unsigned rem = ub - ii * (unsigned)nbc;
            unsigned jj = rem / (unsigned)nc;
            unsigned kk = rem - jj * (unsigned)nc;
            float fi = (float)((int)ii - a_max);
            float fj = (float)((int)jj - b_max);
            float fk = (float)((int)kk - c_max);
            float x = fi * c00 + fj * c10 + fk * c20 + drx;
            float y = fi * c01 + fj * c11 + fk * c21 + dry;
            float z = fi * c02 + fj * c12 + fk * c22 + drz;
            bool m = (x * x + y * y + z * z) < cut2;
            vb[(size_t)idx * 3 + 0] = m ? x : 0.0f;
            vb[(size_t)idx * 3 + 1] = m ? y : 0.0f;
            vb[(size_t)idx * 3 + 2] = m ? z : 0.0f;
            qb[(size_t)idx * 3 + 0] = m ? fi : 0.0f;
            qb[(size_t)idx * 3 + 1] = m ? fj : 0.0f;
            qb[(size_t)idx * 3 + 2] = m ? fk : 0.0f;
            mb[idx] = m ? 1.0f : 0.0f;
        }
        return;
    }

    // window shifts for 16B alignment of TMA destinations (per-block B0
    // contributes 0 mod 16 bytes since EPB*4, EPB*12 are multiples of 16)
    const int sq = (4 - ((3 * N) & 3)) & 3;              // q region shift (floats)
    const int Wq = ((3 * EPB - sq) >> 2) << 2;           // q window length (mult of 4)
    const int sm = (4 - ((6 * N) & 3)) & 3;              // mask region shift
    const int Wm = ((EPB - sm) >> 2) << 2;

    {
        int base = B0 + tid * 4;
        unsigned ub = (unsigned)base;
        unsigned ii = ub / (unsigned)nbc;
        unsigned rem = ub - ii * (unsigned)nbc;
        unsigned jj = rem / (unsigned)nc;
        unsigned kk = rem - jj * (unsigned)nc;
        int i = (int)ii - a_max;
        int j = (int)jj - b_max;
        int k = (int)kk - c_max;

        float v[12], q[12], mm4[4];
        #pragma unroll
        for (int e = 0; e < 4; e++) {
            float fi = (float)i, fj = (float)j, fk = (float)k;
            float x = fi * c00 + fj * c10 + fk * c20 + drx;
            float y = fi * c01 + fj * c11 + fk * c21 + dry;
            float z = fi * c02 + fj * c12 + fk * c22 + drz;
            bool m = (x * x + y * y + z * z) < cut2;
            v[3 * e + 0] = m ? x : 0.0f;
            v[3 * e + 1] = m ? y : 0.0f;
            v[3 * e + 2] = m ? z : 0.0f;
            q[3 * e + 0] = m ? fi : 0.0f;
            q[3 * e + 1] = m ? fj : 0.0f;
            q[3 * e + 2] = m ? fk : 0.0f;
            mm4[e] = m ? 1.0f : 0.0f;
            k++;
            if (k > c_max) {
                k = -c_max;
                j++;
                if (j > b_max) {
                    j = -b_max;
                    i++;
                }
            }
        }

        // v: aligned region, STS.128 x3 (conflict-free: 48B lane stride)
        float4* sv = (float4*)(S + tid * 12);
        sv[0] = make_float4(v[0], v[1], v[2], v[3]);
        sv[1] = make_float4(v[4], v[5], v[6], v[7]);
        sv[2] = make_float4(v[8], v[9], v[10], v[11]);

        // q: shifted window into smem; the <=4 out-of-window floats per block
        // go straight to gmem as scalars
        #pragma unroll
        for (int f = 0; f < 12; f++) {
            int lf = tid * 12 + f;
            int p = lf - sq;
            if ((unsigned)p < (unsigned)Wq) S[OFF_Q + p] = q[f];
            else qb[(size_t)B0 * 3 + lf] = q[f];
        }

        // mask: same scheme
        #pragma unroll
        for (int f = 0; f < 4; f++) {
            int lf = tid * 4 + f;
            int p = lf - sm;
            if ((unsigned)p < (unsigned)Wm) S[OFF_M + p] = mm4[f];
            else mb[(size_t)B0 + lf] = mm4[f];
        }
    }
    __syncthreads();

    if (tid == 0) {
        asm volatile("fence.proxy.async.shared::cta;" ::: "memory");
        uint32_t a_v = smem_u32(S);
        uint32_t a_q = smem_u32(S + OFF_Q);
        uint32_t a_m = smem_u32(S + OFF_M);
        float* dv = vb + (size_t)B0 * 3;
        float* dq = qb + (size_t)B0 * 3 + sq;
        float* dm = mb + (size_t)B0 + sm;
        int bq = Wq * 4;
        int bm = Wm * 4;
        asm volatile("cp.async.bulk.global.shared::cta.bulk_group [%0], [%1], %2;"
                     :: "l"(dv), "r"(a_v), "r"(EPB * 12) : "memory");
        asm volatile("cp.async.bulk.global.shared::cta.bulk_group [%0], [%1], %2;"
                     :: "l"(dq), "r"(a_q), "r"(bq) : "memory");
        asm volatile("cp.async.bulk.global.shared::cta.bulk_group [%0], [%1], %2;"
                     :: "l"(dm), "r"(a_m), "r"(bm) : "memory");
        asm volatile("cp.async.bulk.commit_group;" ::: "memory");
        // guard smem reuse: block must not retire while TMA still reads S
        asm volatile("cp.async.bulk.wait_group 0;" ::: "memory");
    }
}

extern "C" void kernel_launch(void* const* d_in, const int* in_sizes, int n_in,
                              void* d_out, int out_size) {
    const float* cell   = (const float*)d_in[0];
    const float* cutoff = (const float*)d_in[1];
    const float* r1     = (const float*)d_in[2];
    const float* r2     = (const float*)d_in[3];
    float* out = (float*)d_out;

    long long Nhost = (long long)out_size / 7;
    long long grid = (Nhost + EPB - 1) / EPB;
    if (grid < 1) grid = 1;

    bounds_kernel<<<1, 1>>>(cell, cutoff, r1, r2);
    periodic_kernel<<<(unsigned)grid, BT>>>(cell, cutoff, r1, r2, out);
}